// round 10
// baseline (speedup 1.0000x reference)
#include <cuda_runtime.h>
#include <cuda_bf16.h>
#include <math.h>
#include <stdint.h>

#define BB 8
#define CIN 512
#define C1 256
#define DD 128
#define KK 32
#define NN 9216
#define ROWS (BB*NN)
typedef __nv_bfloat16 bf16;
typedef unsigned int u32;

// ------------- scratch (device globals) -------------
__device__ bf16 g_Xh[ROWS*CIN], g_Xm[ROWS*CIN], g_Xl[ROWS*CIN];      // X (N-major)
__device__ bf16 g_Xch[ROWS*CIN], g_Xcm[ROWS*CIN], g_Xcl[ROWS*CIN];   // X (C-major)
__device__ bf16 g_Wth[C1*CIN], g_Wtm[C1*CIN], g_Wtl[C1*CIN];
__device__ bf16 g_Wph[C1*CIN], g_Wpm[C1*CIN], g_Wpl[C1*CIN];
__device__ bf16 g_Wgh[C1*CIN], g_Wgm[C1*CIN];
__device__ bf16 g_W2h[CIN*C1], g_W2m[CIN*C1];
__device__ bf16 g_W3h[DD*CIN], g_W3m[DD*CIN];
__device__ float g_Gp[64*CIN*CIN];                                   // Gram split-K partials
__device__ bf16 g_GRh[BB*CIN*CIN], g_GRm[BB*CIN*CIN], g_GRl[BB*CIN*CIN];
__device__ bf16 g_T1h[BB*C1*CIN], g_T1m[BB*C1*CIN], g_T1l[BB*C1*CIN];
__device__ float g_Fp[BB*C1*C1];
__device__ bf16 g_Fh[BB*C1*C1], g_Fm[BB*C1*C1];                      // f^T parts
__device__ bf16 g_Wfh[BB*CIN*C1], g_Wfm[BB*CIN*C1];                  // W2·f parts
__device__ bf16 g_Gh[ROWS*C1], g_Gm[ROWS*C1];                        // g activation
__device__ float g_Zt[ROWS*CIN];
__device__ bf16 g_Zh[ROWS*CIN], g_Zm[ROWS*CIN];
__device__ float g_ZDt[ROWS*DD];
__device__ float g_sx[BB*CIN];                                       // row sums of X
__device__ float g_bth[BB*C1], g_bph[BB*C1];                         // Wθ·sx, Wφ·sx
__device__ float g_Eacc[BB*KK*DD], g_Asum[BB*KK], g_Es[BB*DD], g_gam[BB*CIN];

// ------------- helpers -------------
__device__ __forceinline__ u32 smem_u32(const void* p) {
    u32 a;
    asm("{ .reg .u64 t; cvta.to.shared.u64 t, %1; cvt.u32.u64 %0, t; }" : "=r"(a) : "l"(p));
    return a;
}
__device__ __forceinline__ void cp16(u32 d, const void* s) {
    asm volatile("cp.async.cg.shared.global [%0], [%1], 16;" :: "r"(d), "l"(s));
}
__device__ __forceinline__ void cp_commit() { asm volatile("cp.async.commit_group;" ::: "memory"); }
template<int N> __device__ __forceinline__ void cp_waitg() {
    asm volatile("cp.async.wait_group %0;" :: "n"(N) : "memory");
}
__device__ __forceinline__ void ldm_x4(u32* r, u32 addr) {
    asm volatile("ldmatrix.sync.aligned.m8n8.x4.shared.b16 {%0,%1,%2,%3}, [%4];"
        : "=r"(r[0]), "=r"(r[1]), "=r"(r[2]), "=r"(r[3]) : "r"(addr));
}
__device__ __forceinline__ void mma16816(float* d, const u32* a, const u32* b) {
    asm volatile(
        "mma.sync.aligned.m16n8k16.row.col.f32.bf16.bf16.f32 "
        "{%0,%1,%2,%3}, {%4,%5,%6,%7}, {%8,%9}, {%0,%1,%2,%3};"
        : "+f"(d[0]), "+f"(d[1]), "+f"(d[2]), "+f"(d[3])
        : "r"(a[0]), "r"(a[1]), "r"(a[2]), "r"(a[3]), "r"(b[0]), "r"(b[1]));
}
__device__ __forceinline__ float2 rd2bf(const bf16* p, long i) {
    u32 v = *(const u32*)(p + i);
    __nv_bfloat162 b = *(__nv_bfloat162*)&v;
    return make_float2(__bfloat162float(b.x), __bfloat162float(b.y));
}
__device__ __forceinline__ void st2bf(bf16* p, long i, float a, float b_) {
    __nv_bfloat162 v(__float2bfloat16(a), __float2bfloat16(b_));
    *(u32*)(p + i) = *(u32*)&v;
}

// ============ mma.sync bf16-split GEMM, product-shared tiles, BK=32 ============
// C[z; m, n] = sum over triangular products A_pa * B_pb (pa+pb<NB), K-major.
// SYM: blockIdx.x indexes lower-triangle 128x128 tile pairs of a 512x512 output.
template<int NPROD, bool SYM>
__global__ __launch_bounds__(256, 2) void mma_gemm(
    const bf16* __restrict__ Ah, const bf16* __restrict__ Am, const bf16* __restrict__ Al,
    int lda, long sAb,
    const bf16* __restrict__ Bh, const bf16* __restrict__ Bm, const bf16* __restrict__ Bl,
    int ldb, long sBb,
    float* __restrict__ C, bf16* __restrict__ Ch, bf16* __restrict__ Cm, bf16* __restrict__ Cl,
    int ldc, long sCz,
    const float* __restrict__ biasC, const float* __restrict__ biasR,
    const bf16* __restrict__ Rh, const bf16* __restrict__ Rm, const bf16* __restrict__ Rl,
    int NCH, int S)
{
    constexpr int NA = (NPROD == 6) ? 3 : 2;
    constexpr int NB = NA;
    constexpr int STAGE = (NA + NB) * 8192;

    extern __shared__ __align__(16) char smem[];
    const u32 sbase = smem_u32(smem);

    const int tid = threadIdx.x, lane = tid & 31, wid = tid >> 5;
    const int wm = wid & 1, wn = wid >> 1;
    const int z = blockIdx.z, b = z / S, s = z % S;
    int bx, by;
    if (SYM) {
        int p = blockIdx.x;
        by = (p < 1) ? 0 : (p < 3) ? 1 : (p < 6) ? 2 : 3;
        bx = p - (by * (by + 1)) / 2;
    } else { bx = blockIdx.x; by = blockIdx.y; }
    const long m0 = (long)by * 128;
    const int n0 = bx * 128;
    const int KS = NCH * 32;

    const long abase = (long)b * sAb + m0 * lda + (long)s * KS;
    const long bbase = (long)b * sBb + (long)n0 * ldb + (long)s * KS;

    const bf16* APT[3] = {Ah, Am, Al};
    const bf16* BPT[3] = {Bh, Bm, Bl};

    float acc[4][4][4];
#pragma unroll
    for (int i = 0; i < 4; i++)
#pragma unroll
        for (int j = 0; j < 4; j++)
#pragma unroll
            for (int r = 0; r < 4; r++) acc[i][j][r] = 0.f;

    const int row2 = tid >> 1, lq = tid & 1;
    const int sw = (row2 >> 1) & 3;
    const u32 c0off = (u32)(row2 * 64 + (((lq * 2 + 0) ^ sw) << 4));
    const u32 c1off = (u32)(row2 * 64 + (((lq * 2 + 1) ^ sw) << 4));

    auto issue = [&](int c) {
        int k0 = c * 32;
        u32 sd = sbase + (c & 1) * STAGE;
#pragma unroll
        for (int p = 0; p < NA; p++) {
            const bf16* ap = APT[p] + abase + k0 + (long)row2 * lda + lq * 16;
            cp16(sd + p * 8192 + c0off, ap);
            cp16(sd + p * 8192 + c1off, ap + 8);
        }
#pragma unroll
        for (int p = 0; p < NB; p++) {
            const bf16* bp = BPT[p] + bbase + k0 + (long)row2 * ldb + lq * 16;
            cp16(sd + (NA + p) * 8192 + c0off, bp);
            cp16(sd + (NA + p) * 8192 + c1off, bp + 8);
        }
        cp_commit();
    };

    u32 aoff[4], boff[2];
#pragma unroll
    for (int t = 0; t < 4; t++) {
        int ra = wm * 64 + t * 16 + (lane & 15);
        int j = lane >> 4;
        aoff[t] = (u32)(ra * 64 + ((j ^ ((ra >> 1) & 3)) << 4));
    }
#pragma unroll
    for (int u = 0; u < 2; u++) {
        int rb = wn * 32 + u * 16 + (lane & 7) + ((lane >> 4) & 1) * 8;
        int j = (lane >> 3) & 1;
        boff[u] = (u32)(rb * 64 + ((j ^ ((rb >> 1) & 3)) << 4));
    }

    issue(0);
    for (int c = 0; c < NCH; c++) {
        if (c + 1 < NCH) { issue(c + 1); cp_waitg<1>(); }
        else cp_waitg<0>();
        __syncthreads();
        u32 sA = sbase + (c & 1) * STAGE;
        u32 sB = sA + NA * 8192;
#pragma unroll
        for (int kk = 0; kk < 2; kk++) {
            u32 kx = kk << 5;
            u32 bfr[NB][2][4];
#pragma unroll
            for (int pb = 0; pb < NB; pb++)
#pragma unroll
                for (int u = 0; u < 2; u++)
                    ldm_x4(bfr[pb][u], sB + pb * 8192 + (boff[u] ^ kx));
#pragma unroll
            for (int pa = 0; pa < NA; pa++) {
                u32 af[4][4];
#pragma unroll
                for (int t = 0; t < 4; t++)
                    ldm_x4(af[t], sA + pa * 8192 + (aoff[t] ^ kx));
#pragma unroll
                for (int pb = 0; pb < NB; pb++) {
                    if (pa + pb < NB) {
#pragma unroll
                        for (int mi = 0; mi < 4; mi++)
#pragma unroll
                            for (int ni = 0; ni < 4; ni++)
                                mma16816(acc[mi][ni], af[mi], &bfr[pb][ni >> 1][(ni & 1) * 2]);
                    }
                }
            }
        }
        __syncthreads();
    }

    // ---- epilogue ----
    const int mrow = lane >> 2, nc2 = (lane & 3) * 2;
#pragma unroll
    for (int mi = 0; mi < 4; mi++) {
#pragma unroll
        for (int rp = 0; rp < 2; rp++) {
            long row = m0 + wm * 64 + mi * 16 + mrow + rp * 8;
            long rowoff = (long)z * sCz + row * ldc;
            float br = biasR ? biasR[row] : 0.f;
#pragma unroll
            for (int ni = 0; ni < 4; ni++) {
                int col = n0 + wn * 32 + ni * 8 + nc2;
                float v0 = acc[mi][ni][rp * 2 + 0] + br;
                float v1 = acc[mi][ni][rp * 2 + 1] + br;
                if (biasC) { v0 += biasC[col]; v1 += biasC[col + 1]; }
                if (Rh) {
                    float2 h = rd2bf(Rh, rowoff + col);
                    float2 m = rd2bf(Rm, rowoff + col);
                    float2 l = rd2bf(Rl, rowoff + col);
                    v0 += h.x + m.x + l.x;
                    v1 += h.y + m.y + l.y;
                }
                if (C) *(float2*)&C[rowoff + col] = make_float2(v0, v1);
                if (Ch) {
                    float h0 = __bfloat162float(__float2bfloat16(v0));
                    float h1 = __bfloat162float(__float2bfloat16(v1));
                    st2bf(Ch, rowoff + col, v0, v1);
                    float r0 = v0 - h0, r1 = v1 - h1;
                    st2bf(Cm, rowoff + col, r0, r1);
                    if (Cl) {
                        float m0f = __bfloat162float(__float2bfloat16(r0));
                        float m1f = __bfloat162float(__float2bfloat16(r1));
                        st2bf(Cl, rowoff + col, r0 - m0f, r1 - m1f);
                    }
                }
            }
        }
    }
}

// ------------- X: transpose+split (N-major) AND straight split (C-major) + row sums -------------
__global__ void tsplit2(const float* __restrict__ src)
{
    __shared__ float ts[32][33];
    int b = blockIdx.z;
    long o = (long)b * CIN * NN;
    int c0 = blockIdx.x * 32, r0 = blockIdx.y * 32;   // c0: n-dim, r0: channel
    int tx = threadIdx.x, ty = threadIdx.y;
#pragma unroll
    for (int i = 0; i < 4; i++) {
        int ch = r0 + ty + i * 8;
        long sidx = o + (long)ch * NN + c0 + tx;
        float v = src[sidx];
        ts[ty + i * 8][tx] = v;
        bf16 hh = __float2bfloat16(v);
        float r1 = v - __bfloat162float(hh);
        bf16 mm = __float2bfloat16(r1);
        g_Xch[sidx] = hh; g_Xcm[sidx] = mm;
        g_Xcl[sidx] = __float2bfloat16(r1 - __bfloat162float(mm));
        float sum = v;
#pragma unroll
        for (int off = 16; off; off >>= 1) sum += __shfl_xor_sync(0xffffffffu, sum, off);
        if (tx == 0) atomicAdd(&g_sx[b * CIN + ch], sum);
    }
    __syncthreads();
    // transposed write: v = ts[ch_local=tx][n_local=ty+i*8] = X[r0+tx][c0+ty+i*8]
    // store at X_t[n=c0+ty+i*8][ch=r0+tx]  (coalesced over ch via tx)
#pragma unroll
    for (int i = 0; i < 4; i++) {
        int n = c0 + ty + i * 8;
        float v = ts[tx][ty + i * 8];
        long tdx = (long)b * NN * CIN + (long)n * CIN + (r0 + tx);
        bf16 hh = __float2bfloat16(v);
        float r1 = v - __bfloat162float(hh);
        bf16 mm = __float2bfloat16(r1);
        g_Xh[tdx] = hh; g_Xm[tdx] = mm;
        g_Xl[tdx] = __float2bfloat16(r1 - __bfloat162float(mm));
    }
}

// ------------- all weight splits in one launch -------------
__global__ void split_all(const float* __restrict__ Wt, const float* __restrict__ Wp,
                          const float* __restrict__ Wg, const float* __restrict__ W2,
                          const float* __restrict__ W3)
{
    int i = blockIdx.x * 256 + threadIdx.x;
    if (i < C1 * CIN) {
        float v = Wt[i];
        bf16 h = __float2bfloat16(v); float r1 = v - __bfloat162float(h);
        bf16 m = __float2bfloat16(r1);
        g_Wth[i] = h; g_Wtm[i] = m; g_Wtl[i] = __float2bfloat16(r1 - __bfloat162float(m));
        v = Wp[i];
        h = __float2bfloat16(v); r1 = v - __bfloat162float(h);
        m = __float2bfloat16(r1);
        g_Wph[i] = h; g_Wpm[i] = m; g_Wpl[i] = __float2bfloat16(r1 - __bfloat162float(m));
        v = Wg[i];
        h = __float2bfloat16(v);
        g_Wgh[i] = h; g_Wgm[i] = __float2bfloat16(v - __bfloat162float(h));
        v = W2[i];
        h = __float2bfloat16(v);
        g_W2h[i] = h; g_W2m[i] = __float2bfloat16(v - __bfloat162float(h));
    }
    if (i < DD * CIN) {
        float v = W3[i];
        bf16 h = __float2bfloat16(v);
        g_W3h[i] = h; g_W3m[i] = __float2bfloat16(v - __bfloat162float(h));
    }
}

// ------------- reduce Gram split-K partials (lower-triangle lookup) + 3-way split -------------
__global__ void gram_reduce()
{
    long idx = (long)blockIdx.x * 256 + threadIdx.x;   // over 8*512*512
    int b = (int)(idx >> 18);
    int rem = (int)(idx & 262143);
    int c1 = rem >> 9, c2 = rem & 511;
    long src = (c1 >> 7 >= c2 >> 7) ? ((long)c1 * 512 + c2) : ((long)c2 * 512 + c1);
    float v = 0.f;
#pragma unroll
    for (int s = 0; s < 8; s++) v += g_Gp[(((long)(b * 8 + s)) << 18) + src];
    bf16 h = __float2bfloat16(v);
    float r1 = v - __bfloat162float(h);
    bf16 m = __float2bfloat16(r1);
    g_GRh[idx] = h; g_GRm[idx] = m;
    g_GRl[idx] = __float2bfloat16(r1 - __bfloat162float(m));
}

// ------------- bias rank-1 corrections: bth = Wtheta*sx, bph = Wphi*sx -------------
__global__ void bcorr(const float* __restrict__ Wt, const float* __restrict__ Wp)
{
    int idx = blockIdx.x * 256 + threadIdx.x;   // 2*8*256
    int which = idx >> 11;
    int r = idx & 2047;
    int b = r >> 8, c = r & 255;
    const float* W = which ? Wp : Wt;
    float s = 0.f;
    for (int k = 0; k < CIN; k++) s += W[c * CIN + k] * g_sx[b * CIN + k];
    (which ? g_bph : g_bth)[b * C1 + c] = s;
}

// ------------- softmax over f rows (+bias corrections), transposed bf16 h/m out -------------
__global__ void softmaxT(const float* __restrict__ bth_bias, const float* __restrict__ bph_bias)
{
    int row = blockIdx.x, t = threadIdx.x;
    int b = row >> 8, c = row & 255;
    long base = ((long)b << 16) + c * 256 + t;
    float v = g_Fp[base]
            + bth_bias[c] * g_bph[b * C1 + t]
            + bph_bias[t] * g_bth[b * C1 + c]
            + (float)NN * bth_bias[c] * bph_bias[t];
    __shared__ float sh[256];
    sh[t] = v; __syncthreads();
    for (int o = 128; o; o >>= 1) { if (t < o) sh[t] = fmaxf(sh[t], sh[t + o]); __syncthreads(); }
    float mx = sh[0]; __syncthreads();
    float e = expf(v - mx);
    sh[t] = e; __syncthreads();
    for (int o = 128; o; o >>= 1) { if (t < o) sh[t] += sh[t + o]; __syncthreads(); }
    float r = e / sh[0];
    long o2 = ((long)b << 16) + t * 256 + c;   // transposed: fT[d=t, c]
    bf16 h = __float2bfloat16(r);
    g_Fh[o2] = h;
    g_Fm[o2] = __float2bfloat16(r - __bfloat162float(h));
}

// ------------- zero accumulators -------------
__global__ void zero_kernel() {
    int i = blockIdx.x * blockDim.x + threadIdx.x;
    if (i < BB * KK * DD) g_Eacc[i] = 0.f;
    if (i < BB * KK)      g_Asum[i] = 0.f;
    if (i < BB * DD)      g_Es[i]   = 0.f;
    if (i < BB * CIN)     g_sx[i]   = 0.f;
}

// ------------- fused dist -> softmax(A) -> E accumulation -------------
__global__ __launch_bounds__(256) void encode_kernel(
    const float* __restrict__ ZDt,
    const float* __restrict__ codewords, const float* __restrict__ scale,
    float* __restrict__ Eacc, float* __restrict__ Asum)
{
    int b = blockIdx.y;
    __shared__ float cs[KK][DD + 1];
    __shared__ float cn[KK], sc[KK];
    __shared__ float xs[DD][33];
    __shared__ float Ash[8][KK];
    int tid = threadIdx.x, lane = tid & 31, wid = tid >> 5;

    for (int i = tid; i < KK * DD; i += 256) cs[i >> 7][i & 127] = codewords[i];
    if (tid < KK) sc[tid] = scale[tid];
    __syncthreads();
    if (tid < KK) {
        float s = 0.f;
        for (int d = 0; d < DD; d++) { float c = cs[tid][d]; s += c * c; }
        cn[tid] = s;
    }
    __syncthreads();

    float ereg[16];
#pragma unroll
    for (int i = 0; i < 16; i++) ereg[i] = 0.f;
    float asum_local = 0.f;
    int myk = tid >> 3, myd0 = tid & 7;

    for (int t = blockIdx.x; t < NN / 32; t += gridDim.x) {
        int n0 = t * 32;
#pragma unroll
        for (int r = 0; r < 4; r++) {
            int idx = r * 256 + tid;
            int n = idx >> 5, d4 = (idx & 31) * 4;
            float4 v = *(const float4*)(ZDt + ((long)b * NN + n0 + n) * DD + d4);
            xs[d4][n] = v.x; xs[d4 + 1][n] = v.y; xs[d4 + 2][n] = v.z; xs[d4 + 3][n] = v.w;
        }
        __syncthreads();
        for (int round = 0; round < 4; round++) {
            int n = round * 8 + wid;
            float xx = 0.f;
            for (int d = lane; d < DD; d += 32) { float x = xs[d][n]; xx += x * x; }
            for (int o = 16; o; o >>= 1) xx += __shfl_xor_sync(0xffffffffu, xx, o);
            float dot = 0.f;
#pragma unroll 8
            for (int d = 0; d < DD; d++) dot += xs[d][n] * cs[lane][d];
            float s = sc[lane] * (xx - 2.f * dot + cn[lane]);
            float mx = s;
            for (int o = 16; o; o >>= 1) mx = fmaxf(mx, __shfl_xor_sync(0xffffffffu, mx, o));
            float e = __expf(s - mx);
            float ssum = e;
            for (int o = 16; o; o >>= 1) ssum += __shfl_xor_sync(0xffffffffu, ssum, o);
            float a = e / ssum;
            Ash[wid][lane] = a;
            asum_local += a;
            __syncthreads();
#pragma unroll
            for (int nn2 = 0; nn2 < 8; nn2++) {
                float av = Ash[nn2][myk];
                int ncol = round * 8 + nn2;
#pragma unroll
                for (int i = 0; i < 16; i++)
                    ereg[i] += av * xs[myd0 + 8 * i][ncol];
            }
            __syncthreads();
        }
    }
#pragma unroll
    for (int i = 0; i < 16; i++)
        atomicAdd(&Eacc[((long)b * KK + myk) * DD + myd0 + 8 * i], ereg[i]);
    atomicAdd(&Asum[b * KK + lane], asum_local);
}

// ------------- BN over K + Es -------------
__global__ void bn_es_kernel(const float* __restrict__ Eacc, const float* __restrict__ Asum,
                             const float* __restrict__ codewords, float* __restrict__ Es)
{
    int k = blockIdx.x, tid = threadIdx.x;
    __shared__ double shs[256], shs2[256];
    float vals[4];
    double s = 0.0, s2 = 0.0;
#pragma unroll
    for (int i = 0; i < 4; i++) {
        int idx = tid + i * 256;
        int b = idx >> 7, d = idx & 127;
        float v = Eacc[((long)b * KK + k) * DD + d] - Asum[b * KK + k] * codewords[k * DD + d];
        vals[i] = v; s += v; s2 += (double)v * v;
    }
    shs[tid] = s; shs2[tid] = s2; __syncthreads();
    for (int o = 128; o; o >>= 1) {
        if (tid < o) { shs[tid] += shs[tid + o]; shs2[tid] += shs2[tid + o]; }
        __syncthreads();
    }
    double mean = shs[0] / 1024.0;
    double var = shs2[0] / 1024.0 - mean * mean;
    float inv = rsqrtf((float)var + 1e-5f);
    float mf = (float)mean;
#pragma unroll
    for (int i = 0; i < 4; i++) {
        int idx = tid + i * 256;
        int b = idx >> 7, d = idx & 127;
        float e = (vals[i] - mf) * inv;
        if (e > 0.f) atomicAdd(&Es[b * DD + d], e);
    }
}

// ------------- gamma = sigmoid(Es @ W_fc^T + b_fc) -------------
__global__ void gamma_kernel(const float* __restrict__ Es, const float* __restrict__ W_fc,
                             const float* __restrict__ b_fc, float* __restrict__ gam)
{
    int idx = blockIdx.x * blockDim.x + threadIdx.x;
    int b = idx / CIN, c = idx % CIN;
    float s = b_fc[c];
    for (int d = 0; d < DD; d++) s += Es[b * DD + d] * W_fc[c * DD + d];
    gam[idx] = 1.f / (1.f + expf(-s));
}

// ------------- transpose back + gamma scale -> output (B, C, N) -------------
__global__ void tscale_out(const float* __restrict__ Zt, const float* __restrict__ gam,
                           float* __restrict__ out)
{
    __shared__ float ts[32][33];
    int b = blockIdx.z;
    int n0 = blockIdx.x * 32, c0 = blockIdx.y * 32;
    int tx = threadIdx.x, ty = threadIdx.y;
#pragma unroll
    for (int i = 0; i < 4; i++)
        ts[ty + i * 8][tx] = Zt[((long)b * NN + n0 + ty + i * 8) * CIN + c0 + tx];
    __syncthreads();
#pragma unroll
    for (int i = 0; i < 4; i++) {
        int c = c0 + ty + i * 8;
        out[((long)b * CIN + c) * NN + n0 + tx] = ts[tx][ty + i * 8] * gam[b * CIN + c];
    }
}

// ------------- launch -------------
#define GA(T, p, s) T* p; cudaGetSymbolAddress((void**)&p, s)

extern "C" void kernel_launch(void* const* d_in, const int* in_sizes, int n_in,
                              void* d_out, int out_size)
{
    const float* X        = (const float*)d_in[0];
    const float* W_theta  = (const float*)d_in[1];
    const float* b_theta  = (const float*)d_in[2];
    const float* W_phi    = (const float*)d_in[3];
    const float* b_phi    = (const float*)d_in[4];
    const float* W_g      = (const float*)d_in[5];
    const float* b_g      = (const float*)d_in[6];
    const float* W2       = (const float*)d_in[7];
    const float* b2       = (const float*)d_in[8];
    const float* W3       = (const float*)d_in[9];
    const float* b3       = (const float*)d_in[10];
    const float* codewords= (const float*)d_in[11];
    const float* scale    = (const float*)d_in[12];
    const float* W_fc     = (const float*)d_in[13];
    const float* b_fc     = (const float*)d_in[14];

    GA(bf16, Xh, g_Xh); GA(bf16, Xm, g_Xm); GA(bf16, Xl, g_Xl);
    GA(bf16, Xch, g_Xch); GA(bf16, Xcm, g_Xcm); GA(bf16, Xcl, g_Xcl);
    GA(bf16, Wth, g_Wth); GA(bf16, Wtm, g_Wtm); GA(bf16, Wtl, g_Wtl);
    GA(bf16, Wph, g_Wph); GA(bf16, Wpm, g_Wpm); GA(bf16, Wpl, g_Wpl);
    GA(bf16, Wgh, g_Wgh); GA(bf16, Wgm, g_Wgm);
    GA(bf16, W2h, g_W2h); GA(bf16, W2m, g_W2m);
    GA(bf16, W3h, g_W3h); GA(bf16, W3m, g_W3m);
    GA(float, Gp, g_Gp);
    GA(bf16, GRh, g_GRh); GA(bf16, GRm, g_GRm); GA(bf16, GRl, g_GRl);
    GA(bf16, T1h, g_T1h); GA(bf16, T1m, g_T1m); GA(bf16, T1l, g_T1l);
    GA(float, Fp, g_Fp);
    GA(bf16, Fh, g_Fh); GA(bf16, Fm, g_Fm);
    GA(bf16, Wfh, g_Wfh); GA(bf16, Wfm, g_Wfm);
    GA(bf16, Gh, g_Gh); GA(bf16, Gm, g_Gm);
    GA(float, Zt, g_Zt);
    GA(bf16, Zh, g_Zh); GA(bf16, Zm, g_Zm);
    GA(float, ZDt, g_ZDt);
    GA(float, Eacc, g_Eacc); GA(float, Asum, g_Asum);
    GA(float, Es, g_Es); GA(float, gamB, g_gam);

    const int SM6 = 2 * 6 * 8192;   // 98304
    const int SM3 = 2 * 4 * 8192;   // 65536
    cudaFuncSetAttribute((const void*)mma_gemm<6, false>, cudaFuncAttributeMaxDynamicSharedMemorySize, SM6);
    cudaFuncSetAttribute((const void*)mma_gemm<6, true>,  cudaFuncAttributeMaxDynamicSharedMemorySize, SM6);
    cudaFuncSetAttribute((const void*)mma_gemm<3, false>, cudaFuncAttributeMaxDynamicSharedMemorySize, SM3);

    // 1 zero, 2 tsplit2, 3 split_all, 4 Gram, 5 gram_reduce, 6 g GEMM (ncu target)
    zero_kernel<<<128, 256>>>();
    tsplit2<<<dim3(288, 16, BB), dim3(32, 8)>>>(X);
    split_all<<<512, 256>>>(W_theta, W_phi, W_g, W2, W3);

    // Gram: G = X·X^T per batch, lower-triangle 128-tiles, split-K=8 (KS=1152, NCH=36)
    mma_gemm<6, true><<<dim3(10, 1, 64), 256, SM6>>>(
        Xch, Xcm, Xcl, NN, (long)CIN * NN, Xch, Xcm, Xcl, NN, (long)CIN * NN,
        Gp, nullptr, nullptr, nullptr, CIN, (long)CIN * CIN,
        nullptr, nullptr, nullptr, nullptr, nullptr, 36, 8);
    gram_reduce<<<8192, 256>>>();

    // g activation: (B·N x 256) = X_t @ Wg^T, x3
    mma_gemm<3, false><<<dim3(2, 576, 1), 256, SM3>>>(
        Xh, Xm, nullptr, CIN, 0, Wgh, Wgm, nullptr, CIN, 0,
        nullptr, Gh, Gm, nullptr, C1, 0, b_g, nullptr, nullptr, nullptr, nullptr,
        16, 1);

    // T1 = Wphi @ G (256 x 512 per batch), x6 -> h/m/l parts
    mma_gemm<6, false><<<dim3(4, 2, BB), 256, SM6>>>(
        Wph, Wpm, Wpl, CIN, 0, GRh, GRm, GRl, CIN, (long)CIN * CIN,
        nullptr, T1h, T1m, T1l, CIN, (long)C1 * CIN,
        nullptr, nullptr, nullptr, nullptr, nullptr, 16, 1);

    // f = Wtheta @ T1^T (256 x 256 per batch), x6 -> fp32
    mma_gemm<6, false><<<dim3(2, 2, BB), 256, SM6>>>(
        Wth, Wtm, Wtl, CIN, 0, T1h, T1m, T1l, CIN, (long)C1 * CIN,
        Fp, nullptr, nullptr, nullptr, C1, (long)C1 * C1,
        nullptr, nullptr, nullptr, nullptr, nullptr, 16, 1);

    bcorr<<<16, 256>>>(W_theta, W_phi);
    softmaxT<<<BB * C1, 256>>>(b_theta, b_phi);

    // Wf = W2 @ f^T (512 x 256 per batch), x3 -> h/m parts
    mma_gemm<3, false><<<dim3(2, 4, BB), 256, SM3>>>(
        W2h, W2m, nullptr, C1, 0, Fh, Fm, nullptr, C1, (long)C1 * C1,
        nullptr, Wfh, Wfm, nullptr, C1, (long)CIN * C1,
        nullptr, nullptr, nullptr, nullptr, nullptr, 8, 1);

    // z = g @ Wf^T + b2 + X (B·N x 512), x3: fp32 + bf16 h/m
    mma_gemm<3, false><<<dim3(4, 72, BB), 256, SM3>>>(
        Gh, Gm, nullptr, C1, (long)NN * C1, Wfh, Wfm, nullptr, C1, (long)CIN * C1,
        Zt, Zh, Zm, nullptr, CIN, (long)NN * CIN, b2, nullptr, Xh, Xm, Xl, 8, 1);

    // z_ = z @ W3^T + b3 (B·N x 128), x3
    mma_gemm<3, false><<<dim3(1, 576, 1), 256, SM3>>>(
        Zh, Zm, nullptr, CIN, 0, W3h, W3m, nullptr, CIN, 0,
        ZDt, nullptr, nullptr, nullptr, DD, 0, b3, nullptr, nullptr, nullptr, nullptr,
        16, 1);

    encode_kernel<<<dim3(96, BB), 256>>>(ZDt, codewords, scale, Eacc, Asum);
    bn_es_kernel<<<KK, 256>>>(Eacc, Asum, codewords, Es);
    gamma_kernel<<<(BB * CIN) / 256, 256>>>(Es, W_fc, b_fc, gamB);
    tscale_out<<<dim3(288, 16, BB), dim3(32, 8)>>>(Zt, gamB, (float*)d_out);
}